// round 2
// baseline (speedup 1.0000x reference)
#include <cuda_runtime.h>
#include <cuda_bf16.h>
#include <cstdint>

// Problem constants
#define Bz   8
#define TQ   64
#define TK   128
#define Dd   512
#define Vv   32000
#define EXTN (Vv + TK)      // 32128
#define NROW (Bz * TQ)      // 512  (b,q) rows
#define NKROW (Bz * TK)     // 1024 (b,k) rows

// ---------------- scratch (device globals; no allocation allowed) ----------
__device__ float g_logits[(size_t)NROW * Vv];   // 65.5 MB
__device__ float g_qproj[NROW * Dd];            // includes b_attn bias
__device__ float g_kproj[NKROW * Dd];
__device__ float g_att[NROW * TK];
__device__ float g_p[NROW];
__device__ float g_rowsum[NROW];
__device__ float g_rowsq[NROW];
__device__ float g_srcmask[NKROW];
__device__ float g_tgtmask[NROW];

// ---------------- helpers ---------------------------------------------------
__device__ __forceinline__ float warp_sum(float v) {
#pragma unroll
    for (int o = 16; o > 0; o >>= 1) v += __shfl_xor_sync(0xffffffffu, v, o);
    return v;
}
__device__ __forceinline__ float warp_max(float v) {
#pragma unroll
    for (int o = 16; o > 0; o >>= 1) v = fmaxf(v, __shfl_xor_sync(0xffffffffu, v, o));
    return v;
}

// block-wide reduction for 256 threads; scr must have >= 9 floats
__device__ __forceinline__ float block_sum256(float v, float* scr) {
    v = warp_sum(v);
    int w = threadIdx.x >> 5;
    __syncthreads();
    if ((threadIdx.x & 31) == 0) scr[w] = v;
    __syncthreads();
    if (threadIdx.x == 0) {
        float t = 0.f;
#pragma unroll
        for (int i = 0; i < 8; i++) t += scr[i];
        scr[8] = t;
    }
    __syncthreads();
    return scr[8];
}
__device__ __forceinline__ float block_max256(float v, float* scr) {
    v = warp_max(v);
    int w = threadIdx.x >> 5;
    __syncthreads();
    if ((threadIdx.x & 31) == 0) scr[w] = v;
    __syncthreads();
    if (threadIdx.x == 0) {
        float t = scr[0];
#pragma unroll
        for (int i = 1; i < 8; i++) t = fmaxf(t, scr[i]);
        scr[8] = t;
    }
    __syncthreads();
    return scr[8];
}

// FMA-only tanh: avoids MUFU.
// tanh(x) = (e^{2x}-1)/(e^{2x}+1); exp2 via magic-round + poly + exponent
// insert; reciprocal via magic constant + 3 Newton steps. abs err ~1e-6.
__device__ __forceinline__ float tanh_fast(float x) {
    float z = x * 2.885390081777927f;             // 2x * log2(e)
    z = fminf(25.f, fmaxf(-25.f, z));
    const float big = 12582912.f;                 // 1.5 * 2^23
    float t  = z + big;
    float nf = t - big;                           // round(z)
    float f  = z - nf;                            // [-0.5, 0.5]
    int   n  = __float_as_int(t) - 0x4B400000;    // integer round(z)
    float p = 1.33335581e-3f;
    p = fmaf(p, f, 9.61804886e-3f);
    p = fmaf(p, f, 5.55041087e-2f);
    p = fmaf(p, f, 2.40226337e-1f);
    p = fmaf(p, f, 6.93147182e-1f);
    p = fmaf(p, f, 1.0f);                         // 2^f
    float y = __int_as_float(__float_as_int(p) + (n << 23));  // e^{2x}
    float d = y + 1.f;
    float r = __int_as_float((int)(0x7EF127EAu - (unsigned)__float_as_int(d)));
    r = r * fmaf(-d, r, 2.f);
    r = r * fmaf(-d, r, 2.f);
    r = r * fmaf(-d, r, 2.f);                     // ~1/(y+1) to ~1e-9 rel
    return (y - 1.f) * r;
}

// ---------------- kernels ---------------------------------------------------
__global__ void init_kernel() {
    int i = blockIdx.x * blockDim.x + threadIdx.x;
    if (i < NROW) { g_rowsum[i] = 0.f; g_rowsq[i] = 0.f; }
}

// masks: blocks 0..511 -> tgt rows, 512..1535 -> src rows. 128 threads.
__global__ void mask_kernel(const float* __restrict__ tgt,
                            const float* __restrict__ src) {
    int rb = blockIdx.x;
    const float* p;
    float* dst;
    if (rb < NROW) { p = tgt + (size_t)rb * Dd; dst = &g_tgtmask[rb]; }
    else           { p = src + (size_t)(rb - NROW) * Dd; dst = &g_srcmask[rb - NROW]; }
    float s = 0.f;
    for (int i = threadIdx.x; i < Dd; i += 128) s += fabsf(p[i]);
    s = warp_sum(s);
    __shared__ float sc[4];
    if ((threadIdx.x & 31) == 0) sc[threadIdx.x >> 5] = s;
    __syncthreads();
    if (threadIdx.x == 0) {
        float tot = sc[0] + sc[1] + sc[2] + sc[3];
        *dst = (tot > 0.f) ? 1.f : 0.f;
    }
}

// SGEMM (NT): C[m,n] = sum_k A[m,k]*B[n,k] + bias[n].
// BM=BN=128, BK=16, 256 threads, 8x8 per thread, register prefetch.
#define BM 128
#define BN 128
#define BK 16
__global__ __launch_bounds__(256, 2)
void sgemm_nt(const float* __restrict__ A, const float* __restrict__ B,
              const float* __restrict__ bias, int dst,
              int K, int lda, int ldb, int ldc, int do_stats) {
    __shared__ float As[BK][BM];
    __shared__ float Bs[BK][BN];
    __shared__ float red[BM][17];

    float* C = (dst == 0) ? g_qproj : (dst == 1) ? g_kproj : g_logits;

    int tid = threadIdx.x;
    int tx = tid & 15, ty = tid >> 4;
    int m0 = blockIdx.y * BM, n0 = blockIdx.x * BN;

    float acc[8][8];
#pragma unroll
    for (int i = 0; i < 8; i++)
#pragma unroll
        for (int j = 0; j < 8; j++) acc[i][j] = 0.f;

    const int T = K / BK;
    float4 a_reg[2], b_reg[2];

#pragma unroll
    for (int l = 0; l < 2; l++) {
        int lin = tid + l * 256;
        int r = lin >> 2, c = (lin & 3) * 4;
        a_reg[l] = *(const float4*)(A + (size_t)(m0 + r) * lda + c);
        b_reg[l] = *(const float4*)(B + (size_t)(n0 + r) * ldb + c);
    }

    for (int t = 0; t < T; t++) {
#pragma unroll
        for (int l = 0; l < 2; l++) {
            int lin = tid + l * 256;
            int r = lin >> 2, c = (lin & 3) * 4;
            As[c + 0][r] = a_reg[l].x; As[c + 1][r] = a_reg[l].y;
            As[c + 2][r] = a_reg[l].z; As[c + 3][r] = a_reg[l].w;
            Bs[c + 0][r] = b_reg[l].x; Bs[c + 1][r] = b_reg[l].y;
            Bs[c + 2][r] = b_reg[l].z; Bs[c + 3][r] = b_reg[l].w;
        }
        __syncthreads();
        if (t + 1 < T) {
            int k0 = (t + 1) * BK;
#pragma unroll
            for (int l = 0; l < 2; l++) {
                int lin = tid + l * 256;
                int r = lin >> 2, c = (lin & 3) * 4;
                a_reg[l] = *(const float4*)(A + (size_t)(m0 + r) * lda + k0 + c);
                b_reg[l] = *(const float4*)(B + (size_t)(n0 + r) * ldb + k0 + c);
            }
        }
#pragma unroll
        for (int kk = 0; kk < BK; kk++) {
            float a[8], bb[8];
            *(float4*)&a[0]  = *(const float4*)&As[kk][ty * 8];
            *(float4*)&a[4]  = *(const float4*)&As[kk][ty * 8 + 4];
            *(float4*)&bb[0] = *(const float4*)&Bs[kk][tx * 8];
            *(float4*)&bb[4] = *(const float4*)&Bs[kk][tx * 8 + 4];
#pragma unroll
            for (int i = 0; i < 8; i++)
#pragma unroll
                for (int j = 0; j < 8; j++)
                    acc[i][j] = fmaf(a[i], bb[j], acc[i][j]);
        }
        __syncthreads();
    }

    // epilogue: bias, store, per-row partial stats
    float bv[8];
#pragma unroll
    for (int j = 0; j < 8; j++) bv[j] = bias ? bias[n0 + tx * 8 + j] : 0.f;

    float rs[8], rq[8];
#pragma unroll
    for (int i = 0; i < 8; i++) {
        int gr = m0 + ty * 8 + i;
        float* crow = C + (size_t)gr * ldc + n0 + tx * 8;
        float s = 0.f, sq = 0.f;
#pragma unroll
        for (int j = 0; j < 8; j++) {
            float v = acc[i][j] + bv[j];
            crow[j] = v;
            s += v;
            sq = fmaf(v, v, sq);
        }
        rs[i] = s; rq[i] = sq;
    }

    if (do_stats) {
        __syncthreads();
#pragma unroll
        for (int i = 0; i < 8; i++) red[ty * 8 + i][tx] = rs[i];
        __syncthreads();
        if (tid < 128) {
            float s = 0.f;
#pragma unroll
            for (int u = 0; u < 16; u++) s += red[tid][u];
            atomicAdd(&g_rowsum[m0 + tid], s);
        }
        __syncthreads();
#pragma unroll
        for (int i = 0; i < 8; i++) red[ty * 8 + i][tx] = rq[i];
        __syncthreads();
        if (tid < 128) {
            float s = 0.f;
#pragma unroll
            for (int u = 0; u < 16; u++) s += red[tid][u];
            atomicAdd(&g_rowsq[m0 + tid], s);
        }
    }
}

// Fused additive attention per (b,q) row: energy tanh-dot, softmax, weight,
// p=sigmoid(weight . W_lin), layernorm(out_att) -> g_att, g_p.
__global__ __launch_bounds__(256)
void attn_kernel(const float* __restrict__ src, const float* __restrict__ v_w,
                 const float* __restrict__ W_lin, const float* __restrict__ b_lin) {
    __shared__ float qp[Dd];
    __shared__ float vw[Dd];
    __shared__ float sraw[TK];
    __shared__ float sprob[TK];
    __shared__ float scr[9];

    int row = blockIdx.x;            // (b,q)
    int b = row >> 6;
    int tid = threadIdx.x, lane = tid & 31, w = tid >> 5;

    for (int i = tid; i < Dd; i += 256) {
        qp[i] = g_qproj[row * Dd + i];   // already includes b_attn
        vw[i] = v_w[i];
    }
    float tm = g_tgtmask[row];
    __syncthreads();

    float qpr[16], vwr[16];
#pragma unroll
    for (int j = 0; j < 16; j++) {
        qpr[j] = qp[lane + 32 * j];
        vwr[j] = vw[lane + 32 * j];
    }

    // raw attention logits per k (warp per k, 8 warps stride TK)
    for (int k = w; k < TK; k += 8) {
        const float* kp = g_kproj + ((size_t)(b * TK + k)) * Dd;
        float acc = 0.f;
#pragma unroll
        for (int j = 0; j < 16; j++)
            acc += tanh_fast(qpr[j] + __ldg(kp + lane + 32 * j)) * vwr[j];
        acc = warp_sum(acc);
        if (lane == 0) sraw[k] = acc;
    }
    __syncthreads();

    float raw = 0.f, smk = 0.f;
    if (tid < TK) { raw = sraw[tid]; smk = g_srcmask[b * TK + tid]; }
    float masked = (tid < TK) ? ((smk == 0.f) ? -1e30f : raw) : -1e30f;
    float mx = block_max256(masked, scr);
    float e = (tid < TK) ? __expf(masked - mx) : 0.f;
    float ssum = block_sum256(e, scr);
    if (tid < TK) sprob[tid] = e / ssum;

    float oa = (tid < TK) ? raw * smk * tm : 0.f;
    float osum = block_sum256(oa, scr);       // also makes sprob visible
    float osq  = block_sum256(oa * oa, scr);

    // z = (softmax @ src_key) * tm  .  W_lin ; p = sigmoid(z + b_lin)
    float zacc = 0.f;
    for (int d = tid; d < Dd; d += 256) {
        float wv = 0.f;
        const float* sp = src + ((size_t)b * TK) * Dd + d;
#pragma unroll 4
        for (int k = 0; k < TK; k++) wv = fmaf(sprob[k], sp[(size_t)k * Dd], wv);
        wv *= tm;
        zacc = fmaf(wv, W_lin[d], zacc);
    }
    float z = block_sum256(zacc, scr);
    if (tid == 0) g_p[row] = 1.f / (1.f + __expf(-(z + b_lin[0])));

    // layernorm of out_att over TK
    float mean = osum * (1.f / (float)TK);
    float var = osq * (1.f / (float)TK) - mean * mean;
    float inv = rsqrtf(var + 1e-5f);
    if (tid < TK) g_att[row * TK + tid] = (oa - mean) * inv;
}

// Final combine: out[row, j<V] = layernorm(logits) * p ; out[row, j>=V] = 0.
__global__ __launch_bounds__(256)
void combine_kernel(float* __restrict__ out) {
    int row = blockIdx.x;
    float mean = g_rowsum[row] * (1.f / (float)Vv);
    float var = g_rowsq[row] * (1.f / (float)Vv) - mean * mean;
    float inv = rsqrtf(var + 1e-5f);
    float pv = g_p[row];
    float a = inv * pv;
    float c = -mean * inv * pv;
    const float4* lg = (const float4*)(g_logits + (size_t)row * Vv);
    float4* op = (float4*)(out + (size_t)row * EXTN);
    for (int i = threadIdx.x; i < Vv / 4; i += 256) {
        float4 v = lg[i];
        v.x = fmaf(v.x, a, c); v.y = fmaf(v.y, a, c);
        v.z = fmaf(v.z, a, c); v.w = fmaf(v.w, a, c);
        op[i] = v;
    }
    for (int j = Vv + threadIdx.x; j < EXTN; j += 256)
        out[(size_t)row * EXTN + j] = 0.f;
}

// Scatter: out[row, map[b,k]] += (1-p[row]) * att[row,k]
// NOTE: src_map_idx is int32 on the wire (JAX x64-disabled truncates the
// requested int64 to int32). Bounds-guarded so a dtype surprise shows up as
// rel_err, not an illegal access.
__global__ void scatter_kernel(float* __restrict__ out,
                               const int* __restrict__ map) {
    int row = blockIdx.x;
    int b = row >> 6;
    float q = 1.f - g_p[row];
    for (int k = threadIdx.x; k < TK; k += blockDim.x) {
        int idx = map[b * TK + k];
        if (idx >= 0 && idx < EXTN)
            atomicAdd(out + (size_t)row * EXTN + (size_t)idx,
                      q * g_att[row * TK + k]);
    }
}

// ---------------- launch -----------------------------------------------------
extern "C" void kernel_launch(void* const* d_in, const int* in_sizes, int n_in,
                              void* d_out, int out_size) {
    const float* tgt    = (const float*)d_in[0];
    const float* src    = (const float*)d_in[1];
    const int*   mp     = (const int*)d_in[2];
    const float* W_out  = (const float*)d_in[3];
    const float* b_out  = (const float*)d_in[4];
    const float* W_attn = (const float*)d_in[5];
    const float* b_attn = (const float*)d_in[6];
    const float* v_w    = (const float*)d_in[7];
    const float* W_lin  = (const float*)d_in[8];
    const float* b_lin  = (const float*)d_in[9];
    float* out = (float*)d_out;

    init_kernel<<<2, 256>>>();
    mask_kernel<<<NROW + NKROW, 128>>>(tgt, src);

    // q_proj = tgt @ Wq^T + b_attn   (Wq rows of W_attn, cols [0,D))
    sgemm_nt<<<dim3(Dd / BN, NROW / BM), 256>>>(tgt, W_attn, b_attn, 0,
                                                Dd, Dd, 2 * Dd, Dd, 0);
    // k_proj = src @ Wk^T            (Wk = W_attn cols [D,2D))
    sgemm_nt<<<dim3(Dd / BN, NKROW / BM), 256>>>(src, W_attn + Dd, nullptr, 1,
                                                 Dd, Dd, 2 * Dd, Dd, 0);
    // logits = tgt @ W_out^T + b_out  (+ per-row sum/sumsq stats)
    sgemm_nt<<<dim3(Vv / BN, NROW / BM), 256>>>(tgt, W_out, b_out, 2,
                                                Dd, Dd, Dd, Vv, 1);

    attn_kernel<<<NROW, 256>>>(src, v_w, W_lin, b_lin);
    combine_kernel<<<NROW, 256>>>(out);
    scatter_kernel<<<NROW, 128>>>(out, mp);
}

// round 8
// speedup vs baseline: 1.6986x; 1.6986x over previous
#include <cuda_runtime.h>
#include <cuda_bf16.h>
#include <cstdint>

// Problem constants
#define Bz   8
#define TQ   64
#define TK   128
#define Dd   512
#define Vv   32000
#define EXTN (Vv + TK)      // 32128
#define NROW (Bz * TQ)      // 512
#define NKROW (Bz * TK)     // 1024

// ---------------- scratch (device globals; ~3.3 MB total) --------------------
__device__ float g_qproj[NROW * Dd];
__device__ float g_kproj[NKROW * Dd];
__device__ float g_att[NROW * TK];
__device__ float g_p[NROW];
__device__ float g_rowsum[NROW];
__device__ float g_rowsq[NROW];
__device__ float g_srcmask[NKROW];
__device__ float g_tgtmask[NROW];

// ---------------- generic helpers -------------------------------------------
__device__ __forceinline__ float warp_sum(float v) {
#pragma unroll
    for (int o = 16; o > 0; o >>= 1) v += __shfl_xor_sync(0xffffffffu, v, o);
    return v;
}
__device__ __forceinline__ float warp_max(float v) {
#pragma unroll
    for (int o = 16; o > 0; o >>= 1) v = fmaxf(v, __shfl_xor_sync(0xffffffffu, v, o));
    return v;
}
__device__ __forceinline__ float block_sum256(float v, float* scr) {
    v = warp_sum(v);
    int w = threadIdx.x >> 5;
    __syncthreads();
    if ((threadIdx.x & 31) == 0) scr[w] = v;
    __syncthreads();
    if (threadIdx.x == 0) {
        float t = 0.f;
#pragma unroll
        for (int i = 0; i < 8; i++) t += scr[i];
        scr[8] = t;
    }
    __syncthreads();
    return scr[8];
}
__device__ __forceinline__ float block_max256(float v, float* scr) {
    v = warp_max(v);
    int w = threadIdx.x >> 5;
    __syncthreads();
    if ((threadIdx.x & 31) == 0) scr[w] = v;
    __syncthreads();
    if (threadIdx.x == 0) {
        float t = scr[0];
#pragma unroll
        for (int i = 1; i < 8; i++) t = fmaxf(t, scr[i]);
        scr[8] = t;
    }
    __syncthreads();
    return scr[8];
}

// FMA-only tanh (proven in the passing round)
__device__ __forceinline__ float tanh_fast(float x) {
    float z = x * 2.885390081777927f;             // 2x * log2(e)
    z = fminf(25.f, fmaxf(-25.f, z));
    const float big = 12582912.f;                 // 1.5 * 2^23
    float t  = z + big;
    float nf = t - big;
    float f  = z - nf;
    int   n  = __float_as_int(t) - 0x4B400000;
    float p = 1.33335581e-3f;
    p = fmaf(p, f, 9.61804886e-3f);
    p = fmaf(p, f, 5.55041087e-2f);
    p = fmaf(p, f, 2.40226337e-1f);
    p = fmaf(p, f, 6.93147182e-1f);
    p = fmaf(p, f, 1.0f);
    float y = __int_as_float(__float_as_int(p) + (n << 23));  // e^{2x}
    float d = y + 1.f;
    float r = __int_as_float((int)(0x7EF127EAu - (unsigned)__float_as_int(d)));
    r = r * fmaf(-d, r, 2.f);
    r = r * fmaf(-d, r, 2.f);
    r = r * fmaf(-d, r, 2.f);
    return (y - 1.f) * r;
}
__device__ __forceinline__ uint32_t smem_u32(const void* p) {
    uint32_t a;
    asm("{ .reg .u64 t; cvta.to.shared.u64 t, %1; cvt.u32.u64 %0, t; }"
        : "=r"(a) : "l"(p));
    return a;
}

// value-only fragment types
struct U4 { uint32_t x, y, z, w; };
struct F4 { float x, y, z, w; };

__device__ __forceinline__ U4 ldmx4(uint32_t addr) {
    U4 r;
    asm volatile("ldmatrix.sync.aligned.m8n8.x4.shared.b16 {%0,%1,%2,%3}, [%4];"
                 : "=r"(r.x), "=r"(r.y), "=r"(r.z), "=r"(r.w) : "r"(addr));
    return r;
}
__device__ __forceinline__ void mma(F4& d, const U4& a, uint32_t b0, uint32_t b1) {
    asm volatile("mma.sync.aligned.m16n8k16.row.col.f32.bf16.bf16.f32 "
        "{%0,%1,%2,%3}, {%4,%5,%6,%7}, {%8,%9}, {%0,%1,%2,%3};"
        : "+f"(d.x), "+f"(d.y), "+f"(d.z), "+f"(d.w)
        : "r"(a.x), "r"(a.y), "r"(a.z), "r"(a.w), "r"(b0), "r"(b1));
}
__device__ __forceinline__ void sts8(uint32_t addr, uint32_t v0, uint32_t v1) {
    asm volatile("st.shared.v2.u32 [%0], {%1, %2};" :: "r"(addr), "r"(v0), "r"(v1));
}

// fp32x4 -> packed bf16x2 hi / lo (split: x = hi + lo)
__device__ __forceinline__ void split4(float4 v, uint2& h, uint2& l) {
    __nv_bfloat16 h0 = __float2bfloat16(v.x), h1 = __float2bfloat16(v.y);
    __nv_bfloat16 h2 = __float2bfloat16(v.z), h3 = __float2bfloat16(v.w);
    __nv_bfloat16 a0 = __float2bfloat16(v.x - __bfloat162float(h0));
    __nv_bfloat16 a1 = __float2bfloat16(v.y - __bfloat162float(h1));
    __nv_bfloat16 a2 = __float2bfloat16(v.z - __bfloat162float(h2));
    __nv_bfloat16 a3 = __float2bfloat16(v.w - __bfloat162float(h3));
    h.x = (uint32_t)__bfloat16_as_ushort(h0) | ((uint32_t)__bfloat16_as_ushort(h1) << 16);
    h.y = (uint32_t)__bfloat16_as_ushort(h2) | ((uint32_t)__bfloat16_as_ushort(h3) << 16);
    l.x = (uint32_t)__bfloat16_as_ushort(a0) | ((uint32_t)__bfloat16_as_ushort(a1) << 16);
    l.y = (uint32_t)__bfloat16_as_ushort(a2) | ((uint32_t)__bfloat16_as_ushort(a3) << 16);
}

// ---------------- small kernels ----------------------------------------------
__global__ void init_kernel() {
    int i = blockIdx.x * blockDim.x + threadIdx.x;
    if (i < NROW) { g_rowsum[i] = 0.f; g_rowsq[i] = 0.f; }
}

__global__ void mask_kernel(const float* __restrict__ tgt,
                            const float* __restrict__ src) {
    int rb = blockIdx.x;
    const float* p;
    float* dst;
    if (rb < NROW) { p = tgt + (size_t)rb * Dd; dst = &g_tgtmask[rb]; }
    else           { p = src + (size_t)(rb - NROW) * Dd; dst = &g_srcmask[rb - NROW]; }
    float s = 0.f;
    for (int i = threadIdx.x; i < Dd; i += 128) s += fabsf(p[i]);
    s = warp_sum(s);
    __shared__ float sc[4];
    if ((threadIdx.x & 31) == 0) sc[threadIdx.x >> 5] = s;
    __syncthreads();
    if (threadIdx.x == 0)
        *dst = ((sc[0] + sc[1] + sc[2] + sc[3]) > 0.f) ? 1.f : 0.f;
}

// ---------------- split-bf16 mma.sync GEMM (fp32 in, in-kernel split) --------
// C[m,n] = sum_k A[m,k]*B[n,k] + bias[n]; A,B fp32 row-major (NT).
// Block tile 128x128, BK=16, 512 threads = 16 warps (4Mx4N), warp tile 32x32.
#define TILE_B 6144             // 128 rows * 48B pitch
#define KSTEPS (Dd / 16)        // 32

#define EPI_ONE(e, g)                                                          \
    { float v0 = half ? (e).z : (e).x; float v1 = half ? (e).w : (e).y;        \
      if (bias) { v0 += __ldg(bias + colbase + (g) * 8);                       \
                  v1 += __ldg(bias + colbase + (g) * 8 + 1); }                 \
      *(float2*)(crow + (g) * 8) = make_float2(v0, v1);                        \
      s += v0 + v1; sq += fmaf(v0, v0, v1 * v1); }

__global__ __launch_bounds__(512)
void mma_gemm(const float* __restrict__ A, int lda,
              const float* __restrict__ B, int ldb,
              const float* __restrict__ bias,
              float* __restrict__ C, int ldc, int do_stats) {
    // [stage][tile: 0=Ahi 1=Alo 2=Bhi 3=Blo][128*48]
    __shared__ __align__(16) uint8_t smbuf[2][4][TILE_B];   // 48 KB
    uint32_t smb = smem_u32(smbuf);

    int tid = threadIdx.x, wid = tid >> 5, lane = tid & 31;
    int warp_m = wid >> 2, warp_n = wid & 3;
    size_t m0 = (size_t)blockIdx.y * 128;
    size_t n0 = (size_t)blockIdx.x * 128;

    // loader mapping: thread t handles row = t>>2, float4-chunk c4 = t&3
    int lrow = tid >> 2, lc4 = tid & 3;
    const float* aptr = A + (m0 + (size_t)lrow) * (size_t)lda + lc4 * 4;
    const float* bptr = B + (n0 + (size_t)lrow) * (size_t)ldb + lc4 * 4;
    uint32_t sbase = (uint32_t)(lrow * 48 + lc4 * 8);   // 4 bf16 = 8B

    // ldmatrix lane addressing
    int q = lane >> 3, li = lane & 7;
    uint32_t aoff0 = (uint32_t)((warp_m * 32 + 0  + (q & 1) * 8 + li) * 48 + (q >> 1) * 16);
    uint32_t aoff1 = (uint32_t)((warp_m * 32 + 16 + (q & 1) * 8 + li) * 48 + (q >> 1) * 16);
    uint32_t boff0 = (uint32_t)((warp_n * 32 + 0  + (q >> 1) * 8 + li) * 48 + (q & 1) * 16);
    uint32_t boff1 = (uint32_t)((warp_n * 32 + 16 + (q >> 1) * 8 + li) * 48 + (q & 1) * 16);

    F4 d00, d01, d02, d03, d10, d11, d12, d13;
    d00.x = d00.y = d00.z = d00.w = 0.f;
    d01 = d00; d02 = d00; d03 = d00;
    d10 = d00; d11 = d00; d12 = d00; d13 = d00;

    float4 pa = *(const float4*)(aptr);
    float4 pb = *(const float4*)(bptr);

#pragma unroll 1
    for (int s = 0; s < KSTEPS; s++) {
        int b = s & 1;
        {
            uint32_t base = smb + (uint32_t)(b * 4 * TILE_B) + sbase;
            uint2 h, l;
            split4(pa, h, l);
            sts8(base + 0 * TILE_B, h.x, h.y);
            sts8(base + 1 * TILE_B, l.x, l.y);
            split4(pb, h, l);
            sts8(base + 2 * TILE_B, h.x, h.y);
            sts8(base + 3 * TILE_B, l.x, l.y);
        }
        __syncthreads();
        if (s + 1 < KSTEPS) {
            pa = *(const float4*)(aptr + (s + 1) * 16);
            pb = *(const float4*)(bptr + (s + 1) * 16);
        }

        uint32_t base = smb + (uint32_t)(b * 4 * TILE_B);
        U4 ah0 = ldmx4(base + 0 * TILE_B + aoff0);
        U4 ah1 = ldmx4(base + 0 * TILE_B + aoff1);
        U4 al0 = ldmx4(base + 1 * TILE_B + aoff0);
        U4 al1 = ldmx4(base + 1 * TILE_B + aoff1);

        U4 bb = ldmx4(base + 2 * TILE_B + boff0);       // B-hi, n0..15
        mma(d00, ah0, bb.x, bb.y); mma(d01, ah0, bb.z, bb.w);
        mma(d10, ah1, bb.x, bb.y); mma(d11, ah1, bb.z, bb.w);
        mma(d00, al0, bb.x, bb.y); mma(d01, al0, bb.z, bb.w);
        mma(d10, al1, bb.x, bb.y); mma(d11, al1, bb.z, bb.w);
        bb = ldmx4(base + 3 * TILE_B + boff0);          // B-lo, n0..15
        mma(d00, ah0, bb.x, bb.y); mma(d01, ah0, bb.z, bb.w);
        mma(d10, ah1, bb.x, bb.y); mma(d11, ah1, bb.z, bb.w);
        bb = ldmx4(base + 2 * TILE_B + boff1);          // B-hi, n16..31
        mma(d02, ah0, bb.x, bb.y); mma(d03, ah0, bb.z, bb.w);
        mma(d12, ah1, bb.x, bb.y); mma(d13, ah1, bb.z, bb.w);
        mma(d02, al0, bb.x, bb.y); mma(d03, al0, bb.z, bb.w);
        mma(d12, al1, bb.x, bb.y); mma(d13, al1, bb.z, bb.w);
        bb = ldmx4(base + 3 * TILE_B + boff1);          // B-lo, n16..31
        mma(d02, ah0, bb.x, bb.y); mma(d03, ah0, bb.z, bb.w);
        mma(d12, ah1, bb.x, bb.y); mma(d13, ah1, bb.z, bb.w);
    }

    // epilogue
    int groupl = lane >> 2, subl = lane & 3;
    int colbase = (int)n0 + warp_n * 32 + subl * 2;

#pragma unroll
    for (int half = 0; half < 2; half++) {
        {
            size_t r = m0 + (size_t)(warp_m * 32 + 0 + half * 8 + groupl);
            float* crow = C + r * (size_t)ldc + colbase;
            float s = 0.f, sq = 0.f;
            EPI_ONE(d00, 0) EPI_ONE(d01, 1) EPI_ONE(d02, 2) EPI_ONE(d03, 3)
            if (do_stats) {
                s  += __shfl_xor_sync(0xffffffffu, s, 1);
                s  += __shfl_xor_sync(0xffffffffu, s, 2);
                sq += __shfl_xor_sync(0xffffffffu, sq, 1);
                sq += __shfl_xor_sync(0xffffffffu, sq, 2);
                if (subl == 0) { atomicAdd(&g_rowsum[r], s); atomicAdd(&g_rowsq[r], sq); }
            }
        }
        {
            size_t r = m0 + (size_t)(warp_m * 32 + 16 + half * 8 + groupl);
            float* crow = C + r * (size_t)ldc + colbase;
            float s = 0.f, sq = 0.f;
            EPI_ONE(d10, 0) EPI_ONE(d11, 1) EPI_ONE(d12, 2) EPI_ONE(d13, 3)
            if (do_stats) {
                s  += __shfl_xor_sync(0xffffffffu, s, 1);
                s  += __shfl_xor_sync(0xffffffffu, s, 2);
                sq += __shfl_xor_sync(0xffffffffu, sq, 1);
                sq += __shfl_xor_sync(0xffffffffu, sq, 2);
                if (subl == 0) { atomicAdd(&g_rowsum[r], s); atomicAdd(&g_rowsq[r], sq); }
            }
        }
    }
}

// ---------------- fused additive attention -----------------------------------
__global__ __launch_bounds__(256)
void attn_kernel(const float* __restrict__ src, const float* __restrict__ v_w,
                 const float* __restrict__ W_lin, const float* __restrict__ b_lin) {
    __shared__ float qp[Dd];
    __shared__ float vw[Dd];
    __shared__ float sraw[TK];
    __shared__ float sprob[TK];
    __shared__ float scr[9];

    int row = blockIdx.x;
    int b = row >> 6;
    int tid = threadIdx.x, lane = tid & 31, w = tid >> 5;

    for (int i = tid; i < Dd; i += 256) {
        qp[i] = g_qproj[row * Dd + i];
        vw[i] = v_w[i];
    }
    float tm = g_tgtmask[row];
    __syncthreads();

    float qpr[16], vwr[16];
#pragma unroll
    for (int j = 0; j < 16; j++) {
        qpr[j] = qp[lane + 32 * j];
        vwr[j] = vw[lane + 32 * j];
    }

    for (int k = w; k < TK; k += 8) {
        const float* kp = g_kproj + ((size_t)(b * TK + k)) * Dd;
        float acc = 0.f;
#pragma unroll
        for (int j = 0; j < 16; j++)
            acc += tanh_fast(qpr[j] + __ldg(kp + lane + 32 * j)) * vwr[j];
        acc = warp_sum(acc);
        if (lane == 0) sraw[k] = acc;
    }
    __syncthreads();

    float raw = 0.f, smk = 0.f;
    if (tid < TK) { raw = sraw[tid]; smk = g_srcmask[b * TK + tid]; }
    float masked = (tid < TK) ? ((smk == 0.f) ? -1e30f : raw) : -1e30f;
    float mx = block_max256(masked, scr);
    float e = (tid < TK) ? __expf(masked - mx) : 0.f;
    float ssum = block_sum256(e, scr);
    if (tid < TK) sprob[tid] = e / ssum;

    float oa = (tid < TK) ? raw * smk * tm : 0.f;
    float osum = block_sum256(oa, scr);
    float osq  = block_sum256(oa * oa, scr);

    float zacc = 0.f;
    for (int dd = tid; dd < Dd; dd += 256) {
        float wv = 0.f;
        const float* sp = src + ((size_t)b * TK) * Dd + dd;
#pragma unroll 4
        for (int k = 0; k < TK; k++) wv = fmaf(sprob[k], sp[(size_t)k * Dd], wv);
        wv *= tm;
        zacc = fmaf(wv, W_lin[dd], zacc);
    }
    float z = block_sum256(zacc, scr);
    if (tid == 0) g_p[row] = 1.f / (1.f + __expf(-(z + b_lin[0])));

    float mean = osum * (1.f / (float)TK);
    float var = osq * (1.f / (float)TK) - mean * mean;
    float inv = rsqrtf(var + 1e-5f);
    if (tid < TK) g_att[row * TK + tid] = (oa - mean) * inv;
}

// ---------------- combine (in-place on out) + scatter -------------------------
__global__ __launch_bounds__(256)
void combine_kernel(float* __restrict__ out) {
    int row = blockIdx.x;
    float mean = g_rowsum[row] * (1.f / (float)Vv);
    float var = g_rowsq[row] * (1.f / (float)Vv) - mean * mean;
    float inv = rsqrtf(var + 1e-5f);
    float pv = g_p[row];
    float a = inv * pv;
    float c = -mean * inv * pv;
    float4* op = (float4*)(out + (size_t)row * EXTN);
    for (int i = threadIdx.x; i < Vv / 4; i += 256) {
        float4 v = op[i];
        v.x = fmaf(v.x, a, c); v.y = fmaf(v.y, a, c);
        v.z = fmaf(v.z, a, c); v.w = fmaf(v.w, a, c);
        op[i] = v;
    }
    for (int j = Vv + threadIdx.x; j < EXTN; j += 256)
        out[(size_t)row * EXTN + j] = 0.f;
}

// src_map_idx is int32 on the wire (JAX x64-disabled); bounds-guarded.
__global__ void scatter_kernel(float* __restrict__ out,
                               const int* __restrict__ map) {
    int row = blockIdx.x;
    int b = row >> 6;
    float q = 1.f - g_p[row];
    for (int k = threadIdx.x; k < TK; k += blockDim.x) {
        int idx = map[b * TK + k];
        if (idx >= 0 && idx < EXTN)
            atomicAdd(out + (size_t)row * EXTN + (size_t)idx,
                      q * g_att[row * TK + k]);
    }
}

// ---------------- launch ------------------------------------------------------
extern "C" void kernel_launch(void* const* d_in, const int* in_sizes, int n_in,
                              void* d_out, int out_size) {
    const float* tgt    = (const float*)d_in[0];
    const float* src    = (const float*)d_in[1];
    const int*   mp     = (const int*)d_in[2];
    const float* W_out  = (const float*)d_in[3];
    const float* b_out  = (const float*)d_in[4];
    const float* W_attn = (const float*)d_in[5];
    const float* b_attn = (const float*)d_in[6];
    const float* v_w    = (const float*)d_in[7];
    const float* W_lin  = (const float*)d_in[8];
    const float* b_lin  = (const float*)d_in[9];
    float* out = (float*)d_out;

    init_kernel<<<2, 256>>>();
    mask_kernel<<<NROW + NKROW, 128>>>(tgt, src);

    float* qproj_p;  cudaGetSymbolAddress((void**)&qproj_p, g_qproj);
    float* kproj_p;  cudaGetSymbolAddress((void**)&kproj_p, g_kproj);

    // q_proj = tgt @ Wq^T + b_attn   (Wq[e,d] = W_attn[e*2D + d])
    mma_gemm<<<dim3(Dd / 128, NROW / 128), 512>>>(
        tgt, Dd, W_attn, 2 * Dd, b_attn, qproj_p, Dd, 0);
    // k_proj = src @ Wk^T            (Wk[e,d] = W_attn[e*2D + D + d])
    mma_gemm<<<dim3(Dd / 128, NKROW / 128), 512>>>(
        src, Dd, W_attn + Dd, 2 * Dd, nullptr, kproj_p, Dd, 0);
    // logits = tgt @ W_out^T + b_out, written straight into out (ldc = EXTN)
    mma_gemm<<<dim3(Vv / 128, NROW / 128), 512>>>(
        tgt, Dd, W_out, Dd, b_out, out, EXTN, 1);

    attn_kernel<<<NROW, 256>>>(src, v_w, W_lin, b_lin);
    combine_kernel<<<NROW, 256>>>(out);
    scatter_kernel<<<NROW, 128>>>(out, mp);
}

// round 9
// speedup vs baseline: 1.9944x; 1.1742x over previous
#include <cuda_runtime.h>
#include <cuda_bf16.h>
#include <cstdint>

// Problem constants
#define Bz   8
#define TQ   64
#define TK   128
#define Dd   512
#define Vv   32000
#define EXTN (Vv + TK)      // 32128
#define NROW (Bz * TQ)      // 512
#define NKROW (Bz * TK)     // 1024

// ---------------- scratch (device globals; ~3.3 MB total) --------------------
__device__ float g_qproj[NROW * Dd];
__device__ float g_kproj[NKROW * Dd];
__device__ float g_att[NROW * TK];
__device__ float g_p[NROW];
__device__ float g_rowsum[NROW];
__device__ float g_rowsq[NROW];
__device__ float g_srcmask[NKROW];
__device__ float g_tgtmask[NROW];

// ---------------- generic helpers -------------------------------------------
__device__ __forceinline__ float warp_sum(float v) {
#pragma unroll
    for (int o = 16; o > 0; o >>= 1) v += __shfl_xor_sync(0xffffffffu, v, o);
    return v;
}
__device__ __forceinline__ float warp_max(float v) {
#pragma unroll
    for (int o = 16; o > 0; o >>= 1) v = fmaxf(v, __shfl_xor_sync(0xffffffffu, v, o));
    return v;
}
__device__ __forceinline__ float block_sum256(float v, float* scr) {
    v = warp_sum(v);
    int w = threadIdx.x >> 5;
    __syncthreads();
    if ((threadIdx.x & 31) == 0) scr[w] = v;
    __syncthreads();
    if (threadIdx.x == 0) {
        float t = 0.f;
#pragma unroll
        for (int i = 0; i < 8; i++) t += scr[i];
        scr[8] = t;
    }
    __syncthreads();
    return scr[8];
}
__device__ __forceinline__ float block_max256(float v, float* scr) {
    v = warp_max(v);
    int w = threadIdx.x >> 5;
    __syncthreads();
    if ((threadIdx.x & 31) == 0) scr[w] = v;
    __syncthreads();
    if (threadIdx.x == 0) {
        float t = scr[0];
#pragma unroll
        for (int i = 1; i < 8; i++) t = fmaxf(t, scr[i]);
        scr[8] = t;
    }
    __syncthreads();
    return scr[8];
}

// FMA-only tanh (proven; MUFU tanh would be throughput-bound at 33.5M calls)
__device__ __forceinline__ float tanh_fast(float x) {
    float z = x * 2.885390081777927f;             // 2x * log2(e)
    z = fminf(25.f, fmaxf(-25.f, z));
    const float big = 12582912.f;                 // 1.5 * 2^23
    float t  = z + big;
    float nf = t - big;
    float f  = z - nf;
    int   n  = __float_as_int(t) - 0x4B400000;
    float p = 1.33335581e-3f;
    p = fmaf(p, f, 9.61804886e-3f);
    p = fmaf(p, f, 5.55041087e-2f);
    p = fmaf(p, f, 2.40226337e-1f);
    p = fmaf(p, f, 6.93147182e-1f);
    p = fmaf(p, f, 1.0f);
    float y = __int_as_float(__float_as_int(p) + (n << 23));  // e^{2x}
    float d = y + 1.f;
    float r = __int_as_float((int)(0x7EF127EAu - (unsigned)__float_as_int(d)));
    r = r * fmaf(-d, r, 2.f);
    r = r * fmaf(-d, r, 2.f);
    r = r * fmaf(-d, r, 2.f);
    return (y - 1.f) * r;
}
__device__ __forceinline__ uint32_t smem_u32(const void* p) {
    uint32_t a;
    asm("{ .reg .u64 t; cvta.to.shared.u64 t, %1; cvt.u32.u64 %0, t; }"
        : "=r"(a) : "l"(p));
    return a;
}

// value-only fragment types
struct U4 { uint32_t x, y, z, w; };
struct F4 { float x, y, z, w; };

__device__ __forceinline__ U4 ldmx4(uint32_t addr) {
    U4 r;
    asm volatile("ldmatrix.sync.aligned.m8n8.x4.shared.b16 {%0,%1,%2,%3}, [%4];"
                 : "=r"(r.x), "=r"(r.y), "=r"(r.z), "=r"(r.w) : "r"(addr));
    return r;
}
__device__ __forceinline__ void mma(F4& d, const U4& a, uint32_t b0, uint32_t b1) {
    asm volatile("mma.sync.aligned.m16n8k16.row.col.f32.bf16.bf16.f32 "
        "{%0,%1,%2,%3}, {%4,%5,%6,%7}, {%8,%9}, {%0,%1,%2,%3};"
        : "+f"(d.x), "+f"(d.y), "+f"(d.z), "+f"(d.w)
        : "r"(a.x), "r"(a.y), "r"(a.z), "r"(a.w), "r"(b0), "r"(b1));
}
__device__ __forceinline__ void sts8(uint32_t addr, uint32_t v0, uint32_t v1) {
    asm volatile("st.shared.v2.u32 [%0], {%1, %2};" :: "r"(addr), "r"(v0), "r"(v1));
}

// fp32x4 -> packed bf16x2 hi / lo (split: x = hi + lo)
__device__ __forceinline__ void split4(float4 v, uint2& h, uint2& l) {
    __nv_bfloat16 h0 = __float2bfloat16(v.x), h1 = __float2bfloat16(v.y);
    __nv_bfloat16 h2 = __float2bfloat16(v.z), h3 = __float2bfloat16(v.w);
    __nv_bfloat16 a0 = __float2bfloat16(v.x - __bfloat162float(h0));
    __nv_bfloat16 a1 = __float2bfloat16(v.y - __bfloat162float(h1));
    __nv_bfloat16 a2 = __float2bfloat16(v.z - __bfloat162float(h2));
    __nv_bfloat16 a3 = __float2bfloat16(v.w - __bfloat162float(h3));
    h.x = (uint32_t)__bfloat16_as_ushort(h0) | ((uint32_t)__bfloat16_as_ushort(h1) << 16);
    h.y = (uint32_t)__bfloat16_as_ushort(h2) | ((uint32_t)__bfloat16_as_ushort(h3) << 16);
    l.x = (uint32_t)__bfloat16_as_ushort(a0) | ((uint32_t)__bfloat16_as_ushort(a1) << 16);
    l.y = (uint32_t)__bfloat16_as_ushort(a2) | ((uint32_t)__bfloat16_as_ushort(a3) << 16);
}

// ---------------- small kernels ----------------------------------------------
__global__ void init_kernel() {
    int i = blockIdx.x * blockDim.x + threadIdx.x;
    if (i < NROW) { g_rowsum[i] = 0.f; g_rowsq[i] = 0.f; }
}

__global__ void mask_kernel(const float* __restrict__ tgt,
                            const float* __restrict__ src) {
    int rb = blockIdx.x;
    const float* p;
    float* dst;
    if (rb < NROW) { p = tgt + (size_t)rb * Dd; dst = &g_tgtmask[rb]; }
    else           { p = src + (size_t)(rb - NROW) * Dd; dst = &g_srcmask[rb - NROW]; }
    float s = 0.f;
    for (int i = threadIdx.x; i < Dd; i += 128) s += fabsf(p[i]);
    s = warp_sum(s);
    __shared__ float sc[4];
    if ((threadIdx.x & 31) == 0) sc[threadIdx.x >> 5] = s;
    __syncthreads();
    if (threadIdx.x == 0)
        *dst = ((sc[0] + sc[1] + sc[2] + sc[3]) > 0.f) ? 1.f : 0.f;
}

// ---------------- split-bf16 mma.sync GEMM (fp32 in, in-kernel split) --------
// C[m,n] = sum_k A[m,k]*B[n,k] + bias[n]; A,B fp32 row-major (NT).
// Block tile 128x128, BK=16, 512 threads = 16 warps (4Mx4N), warp tile 32x32.
// Prefetch distance 2 (two register sets, loop unrolled x2 so parity is static)
// so each LDG has ~2 iterations to complete.
#define TILE_B 6144             // 128 rows * 48B pitch
#define KSTEPS (Dd / 16)        // 32

#define EPI_ONE(e, g)                                                          \
    { float v0 = half ? (e).z : (e).x; float v1 = half ? (e).w : (e).y;        \
      if (bias) { v0 += __ldg(bias + colbase + (g) * 8);                       \
                  v1 += __ldg(bias + colbase + (g) * 8 + 1); }                 \
      *(float2*)(crow + (g) * 8) = make_float2(v0, v1);                        \
      s += v0 + v1; sq += fmaf(v0, v0, v1 * v1); }

// ldmatrix + 24 MMA on one buffer (macro so accumulators stay named scalars)
#define MMA_STEP(BASE)                                                          \
    {   uint32_t base_ = (BASE);                                                \
        U4 ah0 = ldmx4(base_ + 0 * TILE_B + aoff0);                             \
        U4 ah1 = ldmx4(base_ + 0 * TILE_B + aoff1);                             \
        U4 al0 = ldmx4(base_ + 1 * TILE_B + aoff0);                             \
        U4 al1 = ldmx4(base_ + 1 * TILE_B + aoff1);                             \
        U4 bb = ldmx4(base_ + 2 * TILE_B + boff0);                              \
        mma(d00, ah0, bb.x, bb.y); mma(d01, ah0, bb.z, bb.w);                   \
        mma(d10, ah1, bb.x, bb.y); mma(d11, ah1, bb.z, bb.w);                   \
        mma(d00, al0, bb.x, bb.y); mma(d01, al0, bb.z, bb.w);                   \
        mma(d10, al1, bb.x, bb.y); mma(d11, al1, bb.z, bb.w);                   \
        bb = ldmx4(base_ + 3 * TILE_B + boff0);                                 \
        mma(d00, ah0, bb.x, bb.y); mma(d01, ah0, bb.z, bb.w);                   \
        mma(d10, ah1, bb.x, bb.y); mma(d11, ah1, bb.z, bb.w);                   \
        bb = ldmx4(base_ + 2 * TILE_B + boff1);                                 \
        mma(d02, ah0, bb.x, bb.y); mma(d03, ah0, bb.z, bb.w);                   \
        mma(d12, ah1, bb.x, bb.y); mma(d13, ah1, bb.z, bb.w);                   \
        mma(d02, al0, bb.x, bb.y); mma(d03, al0, bb.z, bb.w);                   \
        mma(d12, al1, bb.x, bb.y); mma(d13, al1, bb.z, bb.w);                   \
        bb = ldmx4(base_ + 3 * TILE_B + boff1);                                 \
        mma(d02, ah0, bb.x, bb.y); mma(d03, ah0, bb.z, bb.w);                   \
        mma(d12, ah1, bb.x, bb.y); mma(d13, ah1, bb.z, bb.w);                   \
    }

__device__ __forceinline__ void gemm_core(
    const float* __restrict__ A, int lda,
    const float* __restrict__ B, int ldb,
    const float* __restrict__ bias,
    float* __restrict__ C, int ldc, int do_stats,
    size_t m0, size_t n0, uint8_t* smem_raw) {
    uint32_t smb = smem_u32(smem_raw);

    int tid = threadIdx.x, wid = tid >> 5, lane = tid & 31;
    int warp_m = wid >> 2, warp_n = wid & 3;

    // loader mapping: thread t handles row = t>>2, float4-chunk c4 = t&3
    int lrow = tid >> 2, lc4 = tid & 3;
    const float* aptr = A + (m0 + (size_t)lrow) * (size_t)lda + lc4 * 4;
    const float* bptr = B + (n0 + (size_t)lrow) * (size_t)ldb + lc4 * 4;
    uint32_t sbase = (uint32_t)(lrow * 48 + lc4 * 8);   // 4 bf16 = 8B

    // ldmatrix lane addressing
    int q = lane >> 3, li = lane & 7;
    uint32_t aoff0 = (uint32_t)((warp_m * 32 + 0  + (q & 1) * 8 + li) * 48 + (q >> 1) * 16);
    uint32_t aoff1 = (uint32_t)((warp_m * 32 + 16 + (q & 1) * 8 + li) * 48 + (q >> 1) * 16);
    uint32_t boff0 = (uint32_t)((warp_n * 32 + 0  + (q >> 1) * 8 + li) * 48 + (q & 1) * 16);
    uint32_t boff1 = (uint32_t)((warp_n * 32 + 16 + (q >> 1) * 8 + li) * 48 + (q & 1) * 16);

    F4 d00, d01, d02, d03, d10, d11, d12, d13;
    d00.x = d00.y = d00.z = d00.w = 0.f;
    d01 = d00; d02 = d00; d03 = d00;
    d10 = d00; d11 = d00; d12 = d00; d13 = d00;

    // prefetch k-steps 0 and 1
    float4 pa0 = *(const float4*)(aptr);
    float4 pb0 = *(const float4*)(bptr);
    float4 pa1 = *(const float4*)(aptr + 16);
    float4 pb1 = *(const float4*)(bptr + 16);

    uint32_t sb0 = smb + sbase;                       // buffer 0
    uint32_t sb1 = smb + (uint32_t)(4 * TILE_B) + sbase;  // buffer 1

#pragma unroll 1
    for (int s = 0; s < KSTEPS; s += 2) {
        // even step: buffer 0, regs pa0/pb0 (k-step s)
        {
            uint2 h, l;
            split4(pa0, h, l);
            sts8(sb0 + 0 * TILE_B, h.x, h.y);
            sts8(sb0 + 1 * TILE_B, l.x, l.y);
            split4(pb0, h, l);
            sts8(sb0 + 2 * TILE_B, h.x, h.y);
            sts8(sb0 + 3 * TILE_B, l.x, l.y);
        }
        if (s + 2 < KSTEPS) {                         // LDG before barrier
            pa0 = *(const float4*)(aptr + (s + 2) * 16);
            pb0 = *(const float4*)(bptr + (s + 2) * 16);
        }
        __syncthreads();
        MMA_STEP(smb)
        // odd step: buffer 1, regs pa1/pb1 (k-step s+1)
        {
            uint2 h, l;
            split4(pa1, h, l);
            sts8(sb1 + 0 * TILE_B, h.x, h.y);
            sts8(sb1 + 1 * TILE_B, l.x, l.y);
            split4(pb1, h, l);
            sts8(sb1 + 2 * TILE_B, h.x, h.y);
            sts8(sb1 + 3 * TILE_B, l.x, l.y);
        }
        if (s + 3 < KSTEPS) {
            pa1 = *(const float4*)(aptr + (s + 3) * 16);
            pb1 = *(const float4*)(bptr + (s + 3) * 16);
        }
        __syncthreads();
        MMA_STEP(smb + (uint32_t)(4 * TILE_B))
    }

    // epilogue
    int groupl = lane >> 2, subl = lane & 3;
    int colbase = (int)n0 + warp_n * 32 + subl * 2;

#pragma unroll
    for (int half = 0; half < 2; half++) {
        {
            size_t r = m0 + (size_t)(warp_m * 32 + 0 + half * 8 + groupl);
            float* crow = C + r * (size_t)ldc + colbase;
            float s = 0.f, sq = 0.f;
            EPI_ONE(d00, 0) EPI_ONE(d01, 1) EPI_ONE(d02, 2) EPI_ONE(d03, 3)
            if (do_stats) {
                s  += __shfl_xor_sync(0xffffffffu, s, 1);
                s  += __shfl_xor_sync(0xffffffffu, s, 2);
                sq += __shfl_xor_sync(0xffffffffu, sq, 1);
                sq += __shfl_xor_sync(0xffffffffu, sq, 2);
                if (subl == 0) { atomicAdd(&g_rowsum[r], s); atomicAdd(&g_rowsq[r], sq); }
            }
        }
        {
            size_t r = m0 + (size_t)(warp_m * 32 + 16 + half * 8 + groupl);
            float* crow = C + r * (size_t)ldc + colbase;
            float s = 0.f, sq = 0.f;
            EPI_ONE(d10, 0) EPI_ONE(d11, 1) EPI_ONE(d12, 2) EPI_ONE(d13, 3)
            if (do_stats) {
                s  += __shfl_xor_sync(0xffffffffu, s, 1);
                s  += __shfl_xor_sync(0xffffffffu, s, 2);
                sq += __shfl_xor_sync(0xffffffffu, sq, 1);
                sq += __shfl_xor_sync(0xffffffffu, sq, 2);
                if (subl == 0) { atomicAdd(&g_rowsum[r], s); atomicAdd(&g_rowsq[r], sq); }
            }
        }
    }
}

// logits GEMM (also generic)
__global__ __launch_bounds__(512)
void mma_gemm(const float* __restrict__ A, int lda,
              const float* __restrict__ B, int ldb,
              const float* __restrict__ bias,
              float* __restrict__ C, int ldc, int do_stats) {
    __shared__ __align__(16) uint8_t smbuf[2][4][TILE_B];   // 48 KB
    gemm_core(A, lda, B, ldb, bias, C, ldc, do_stats,
              (size_t)blockIdx.y * 128, (size_t)blockIdx.x * 128, &smbuf[0][0][0]);
}

// merged qproj + kproj in one launch: z=0 -> qproj (4 M-blocks), z=1 -> kproj (8)
__global__ __launch_bounds__(512)
void qk_gemm(const float* __restrict__ tgt, const float* __restrict__ src,
             const float* __restrict__ W_attn, const float* __restrict__ b_attn) {
    __shared__ __align__(16) uint8_t smbuf[2][4][TILE_B];
    if (blockIdx.z == 0) {
        if (blockIdx.y >= NROW / 128) return;
        gemm_core(tgt, Dd, W_attn, 2 * Dd, b_attn, g_qproj, Dd, 0,
                  (size_t)blockIdx.y * 128, (size_t)blockIdx.x * 128, &smbuf[0][0][0]);
    } else {
        gemm_core(src, Dd, W_attn + Dd, 2 * Dd, nullptr, g_kproj, Dd, 0,
                  (size_t)blockIdx.y * 128, (size_t)blockIdx.x * 128, &smbuf[0][0][0]);
    }
}

// ---------------- fused additive attention -----------------------------------
__global__ __launch_bounds__(256)
void attn_kernel(const float* __restrict__ src, const float* __restrict__ v_w,
                 const float* __restrict__ W_lin, const float* __restrict__ b_lin) {
    __shared__ float qp[Dd];
    __shared__ float vw[Dd];
    __shared__ float sraw[TK];
    __shared__ float sprob[TK];
    __shared__ float scr[9];

    int row = blockIdx.x;
    int b = row >> 6;
    int tid = threadIdx.x, lane = tid & 31, w = tid >> 5;

    for (int i = tid; i < Dd; i += 256) {
        qp[i] = g_qproj[row * Dd + i];
        vw[i] = v_w[i];
    }
    float tm = g_tgtmask[row];
    __syncthreads();

    float qpr[16], vwr[16];
#pragma unroll
    for (int j = 0; j < 16; j++) {
        qpr[j] = qp[lane + 32 * j];
        vwr[j] = vw[lane + 32 * j];
    }

    for (int k = w; k < TK; k += 8) {
        const float* kp = g_kproj + ((size_t)(b * TK + k)) * Dd;
        float acc = 0.f;
#pragma unroll
        for (int j = 0; j < 16; j++)
            acc += tanh_fast(qpr[j] + __ldg(kp + lane + 32 * j)) * vwr[j];
        acc = warp_sum(acc);
        if (lane == 0) sraw[k] = acc;
    }
    __syncthreads();

    float raw = 0.f, smk = 0.f;
    if (tid < TK) { raw = sraw[tid]; smk = g_srcmask[b * TK + tid]; }
    float masked = (tid < TK) ? ((smk == 0.f) ? -1e30f : raw) : -1e30f;
    float mx = block_max256(masked, scr);
    float e = (tid < TK) ? __expf(masked - mx) : 0.f;
    float ssum = block_sum256(e, scr);
    if (tid < TK) sprob[tid] = e / ssum;

    float oa = (tid < TK) ? raw * smk * tm : 0.f;
    float osum = block_sum256(oa, scr);
    float osq  = block_sum256(oa * oa, scr);

    float zacc = 0.f;
    for (int dd = tid; dd < Dd; dd += 256) {
        float wv = 0.f;
        const float* sp = src + ((size_t)b * TK) * Dd + dd;
#pragma unroll 4
        for (int k = 0; k < TK; k++) wv = fmaf(sprob[k], sp[(size_t)k * Dd], wv);
        wv *= tm;
        zacc = fmaf(wv, W_lin[dd], zacc);
    }
    float z = block_sum256(zacc, scr);
    if (tid == 0) g_p[row] = 1.f / (1.f + __expf(-(z + b_lin[0])));

    float mean = osum * (1.f / (float)TK);
    float var = osq * (1.f / (float)TK) - mean * mean;
    float inv = rsqrtf(var + 1e-5f);
    if (tid < TK) g_att[row * TK + tid] = (oa - mean) * inv;
}

// ---------------- combine (in-place on out) + scatter -------------------------
__global__ __launch_bounds__(256)
void combine_kernel(float* __restrict__ out) {
    int row = blockIdx.x;
    float mean = g_rowsum[row] * (1.f / (float)Vv);
    float var = g_rowsq[row] * (1.f / (float)Vv) - mean * mean;
    float inv = rsqrtf(var + 1e-5f);
    float pv = g_p[row];
    float a = inv * pv;
    float c = -mean * inv * pv;
    float4* op = (float4*)(out + (size_t)row * EXTN);
    for (int i = threadIdx.x; i < Vv / 4; i += 256) {
        float4 v = op[i];
        v.x = fmaf(v.x, a, c); v.y = fmaf(v.y, a, c);
        v.z = fmaf(v.z, a, c); v.w = fmaf(v.w, a, c);
        op[i] = v;
    }
    for (int j = Vv + threadIdx.x; j < EXTN; j += 256)
        out[(size_t)row * EXTN + j] = 0.f;
}

// src_map_idx is int32 on the wire (JAX x64-disabled); bounds-guarded.
__global__ void scatter_kernel(float* __restrict__ out,
                               const int* __restrict__ map) {
    int row = blockIdx.x;
    int b = row >> 6;
    float q = 1.f - g_p[row];
    for (int k = threadIdx.x; k < TK; k += blockDim.x) {
        int idx = map[b * TK + k];
        if (idx >= 0 && idx < EXTN)
            atomicAdd(out + (size_t)row * EXTN + (size_t)idx,
                      q * g_att[row * TK + k]);
    }
}

// ---------------- launch ------------------------------------------------------
extern "C" void kernel_launch(void* const* d_in, const int* in_sizes, int n_in,
                              void* d_out, int out_size) {
    const float* tgt    = (const float*)d_in[0];
    const float* src    = (const float*)d_in[1];
    const int*   mp     = (const int*)d_in[2];
    const float* W_out  = (const float*)d_in[3];
    const float* b_out  = (const float*)d_in[4];
    const float* W_attn = (const float*)d_in[5];
    const float* b_attn = (const float*)d_in[6];
    const float* v_w    = (const float*)d_in[7];
    const float* W_lin  = (const float*)d_in[8];
    const float* b_lin  = (const float*)d_in[9];
    float* out = (float*)d_out;

    init_kernel<<<2, 256>>>();
    mask_kernel<<<NROW + NKROW, 128>>>(tgt, src);

    // qproj + kproj merged (z=0: qproj 4 M-blocks; z=1: kproj 8 M-blocks)
    qk_gemm<<<dim3(Dd / 128, NKROW / 128, 2), 512>>>(tgt, src, W_attn, b_attn);

    // logits = tgt @ W_out^T + b_out, written straight into out (ldc = EXTN)
    mma_gemm<<<dim3(Vv / 128, NROW / 128), 512>>>(
        tgt, Dd, W_out, Dd, b_out, out, EXTN, 1);

    attn_kernel<<<NROW, 256>>>(src, v_w, W_lin, b_lin);
    combine_kernel<<<NROW, 256>>>(out);
    scatter_kernel<<<NROW, 128>>>(out, mp);
}

// round 10
// speedup vs baseline: 2.0971x; 1.0515x over previous
#include <cuda_runtime.h>
#include <cuda_bf16.h>
#include <cstdint>

// Problem constants
#define Bz   8
#define TQ   64
#define TK   128
#define Dd   512
#define Vv   32000
#define EXTN (Vv + TK)      // 32128
#define NROW (Bz * TQ)      // 512
#define NKROW (Bz * TK)     // 1024

// ---------------- scratch (device globals; ~3.3 MB total) --------------------
__device__ float g_qproj[NROW * Dd];
__device__ float g_kproj[NKROW * Dd];
__device__ float g_att[NROW * TK];
__device__ float g_p[NROW];
__device__ float g_rowsum[NROW];
__device__ float g_rowsq[NROW];
__device__ float g_srcmask[NKROW];
__device__ float g_tgtmask[NROW];

// ---------------- generic helpers -------------------------------------------
__device__ __forceinline__ float warp_sum(float v) {
#pragma unroll
    for (int o = 16; o > 0; o >>= 1) v += __shfl_xor_sync(0xffffffffu, v, o);
    return v;
}
__device__ __forceinline__ float warp_max(float v) {
#pragma unroll
    for (int o = 16; o > 0; o >>= 1) v = fmaxf(v, __shfl_xor_sync(0xffffffffu, v, o));
    return v;
}
__device__ __forceinline__ float block_sum256(float v, float* scr) {
    v = warp_sum(v);
    int w = threadIdx.x >> 5;
    __syncthreads();
    if ((threadIdx.x & 31) == 0) scr[w] = v;
    __syncthreads();
    if (threadIdx.x == 0) {
        float t = 0.f;
#pragma unroll
        for (int i = 0; i < 8; i++) t += scr[i];
        scr[8] = t;
    }
    __syncthreads();
    return scr[8];
}
__device__ __forceinline__ float block_max256(float v, float* scr) {
    v = warp_max(v);
    int w = threadIdx.x >> 5;
    __syncthreads();
    if ((threadIdx.x & 31) == 0) scr[w] = v;
    __syncthreads();
    if (threadIdx.x == 0) {
        float t = scr[0];
#pragma unroll
        for (int i = 1; i < 8; i++) t = fmaxf(t, scr[i]);
        scr[8] = t;
    }
    __syncthreads();
    return scr[8];
}

// FMA-only tanh (proven; MUFU tanh would be throughput-bound at 33.5M calls)
__device__ __forceinline__ float tanh_fast(float x) {
    float z = x * 2.885390081777927f;             // 2x * log2(e)
    z = fminf(25.f, fmaxf(-25.f, z));
    const float big = 12582912.f;                 // 1.5 * 2^23
    float t  = z + big;
    float nf = t - big;
    float f  = z - nf;
    int   n  = __float_as_int(t) - 0x4B400000;
    float p = 1.33335581e-3f;
    p = fmaf(p, f, 9.61804886e-3f);
    p = fmaf(p, f, 5.55041087e-2f);
    p = fmaf(p, f, 2.40226337e-1f);
    p = fmaf(p, f, 6.93147182e-1f);
    p = fmaf(p, f, 1.0f);
    float y = __int_as_float(__float_as_int(p) + (n << 23));  // e^{2x}
    float d = y + 1.f;
    float r = __int_as_float((int)(0x7EF127EAu - (unsigned)__float_as_int(d)));
    r = r * fmaf(-d, r, 2.f);
    r = r * fmaf(-d, r, 2.f);
    r = r * fmaf(-d, r, 2.f);
    return (y - 1.f) * r;
}
__device__ __forceinline__ uint32_t smem_u32(const void* p) {
    uint32_t a;
    asm("{ .reg .u64 t; cvta.to.shared.u64 t, %1; cvt.u32.u64 %0, t; }"
        : "=r"(a) : "l"(p));
    return a;
}

// value-only fragment types
struct U4 { uint32_t x, y, z, w; };
struct F4 { float x, y, z, w; };

__device__ __forceinline__ U4 ldmx4(uint32_t addr) {
    U4 r;
    asm volatile("ldmatrix.sync.aligned.m8n8.x4.shared.b16 {%0,%1,%2,%3}, [%4];"
                 : "=r"(r.x), "=r"(r.y), "=r"(r.z), "=r"(r.w) : "r"(addr));
    return r;
}
__device__ __forceinline__ void mma(F4& d, const U4& a, uint32_t b0, uint32_t b1) {
    asm volatile("mma.sync.aligned.m16n8k16.row.col.f32.bf16.bf16.f32 "
        "{%0,%1,%2,%3}, {%4,%5,%6,%7}, {%8,%9}, {%0,%1,%2,%3};"
        : "+f"(d.x), "+f"(d.y), "+f"(d.z), "+f"(d.w)
        : "r"(a.x), "r"(a.y), "r"(a.z), "r"(a.w), "r"(b0), "r"(b1));
}
__device__ __forceinline__ void sts8(uint32_t addr, uint32_t v0, uint32_t v1) {
    asm volatile("st.shared.v2.u32 [%0], {%1, %2};" :: "r"(addr), "r"(v0), "r"(v1));
}
__device__ __forceinline__ void sts16(uint32_t addr, uint32_t v0, uint32_t v1,
                                      uint32_t v2, uint32_t v3) {
    asm volatile("st.shared.v4.u32 [%0], {%1, %2, %3, %4};"
                 :: "r"(addr), "r"(v0), "r"(v1), "r"(v2), "r"(v3));
}

// fp32x4 -> packed bf16x2 hi / lo (split: x = hi + lo)
__device__ __forceinline__ void split4(float4 v, uint2& h, uint2& l) {
    __nv_bfloat16 h0 = __float2bfloat16(v.x), h1 = __float2bfloat16(v.y);
    __nv_bfloat16 h2 = __float2bfloat16(v.z), h3 = __float2bfloat16(v.w);
    __nv_bfloat16 a0 = __float2bfloat16(v.x - __bfloat162float(h0));
    __nv_bfloat16 a1 = __float2bfloat16(v.y - __bfloat162float(h1));
    __nv_bfloat16 a2 = __float2bfloat16(v.z - __bfloat162float(h2));
    __nv_bfloat16 a3 = __float2bfloat16(v.w - __bfloat162float(h3));
    h.x = (uint32_t)__bfloat16_as_ushort(h0) | ((uint32_t)__bfloat16_as_ushort(h1) << 16);
    h.y = (uint32_t)__bfloat16_as_ushort(h2) | ((uint32_t)__bfloat16_as_ushort(h3) << 16);
    l.x = (uint32_t)__bfloat16_as_ushort(a0) | ((uint32_t)__bfloat16_as_ushort(a1) << 16);
    l.y = (uint32_t)__bfloat16_as_ushort(a2) | ((uint32_t)__bfloat16_as_ushort(a3) << 16);
}

// ---------------- small kernels ----------------------------------------------
__global__ void init_kernel() {
    int i = blockIdx.x * blockDim.x + threadIdx.x;
    if (i < NROW) { g_rowsum[i] = 0.f; g_rowsq[i] = 0.f; }
}

__global__ void mask_kernel(const float* __restrict__ tgt,
                            const float* __restrict__ src) {
    int rb = blockIdx.x;
    const float* p;
    float* dst;
    if (rb < NROW) { p = tgt + (size_t)rb * Dd; dst = &g_tgtmask[rb]; }
    else           { p = src + (size_t)(rb - NROW) * Dd; dst = &g_srcmask[rb - NROW]; }
    float s = 0.f;
    for (int i = threadIdx.x; i < Dd; i += 128) s += fabsf(p[i]);
    s = warp_sum(s);
    __shared__ float sc[4];
    if ((threadIdx.x & 31) == 0) sc[threadIdx.x >> 5] = s;
    __syncthreads();
    if (threadIdx.x == 0)
        *dst = ((sc[0] + sc[1] + sc[2] + sc[3]) > 0.f) ? 1.f : 0.f;
}

// ---------------- split-bf16 mma.sync GEMM (fp32 in, in-kernel split) --------
// C[m,n] = sum_k A[m,k]*B[n,k] + bias[n]; A,B fp32 row-major (NT).
// CTA tile 64x128, BK=16, 256 threads = 8 warps (2M x 4N), warp tile 32x32.
// Prefetch distance 2, ping-pong buffers, 2 CTAs per SM (launch_bounds(256,2)).
#define A_TILE_B 3072           // 64 rows * 48B pitch
#define B_TILE_B 6144           // 128 rows * 48B pitch
#define OFF_AHI  0
#define OFF_ALO  3072
#define OFF_BHI  6144
#define OFF_BLO  12288
#define STAGE_B  18432
#define KSTEPS (Dd / 16)        // 32

#define EPI_ONE(e, g)                                                          \
    { float v0 = half ? (e).z : (e).x; float v1 = half ? (e).w : (e).y;        \
      if (bias) { v0 += __ldg(bias + colbase + (g) * 8);                       \
                  v1 += __ldg(bias + colbase + (g) * 8 + 1); }                 \
      *(float2*)(crow + (g) * 8) = make_float2(v0, v1);                        \
      s += v0 + v1; sq += fmaf(v0, v0, v1 * v1); }

// ldmatrix + 24 MMA on one stage
#define MMA_STEP(SBASE)                                                         \
    {   uint32_t sb_ = (SBASE);                                                 \
        U4 ah0 = ldmx4(sb_ + OFF_AHI + aoff0);                                  \
        U4 ah1 = ldmx4(sb_ + OFF_AHI + aoff1);                                  \
        U4 al0 = ldmx4(sb_ + OFF_ALO + aoff0);                                  \
        U4 al1 = ldmx4(sb_ + OFF_ALO + aoff1);                                  \
        U4 bb = ldmx4(sb_ + OFF_BHI + boff0);                                   \
        mma(d00, ah0, bb.x, bb.y); mma(d01, ah0, bb.z, bb.w);                   \
        mma(d10, ah1, bb.x, bb.y); mma(d11, ah1, bb.z, bb.w);                   \
        mma(d00, al0, bb.x, bb.y); mma(d01, al0, bb.z, bb.w);                   \
        mma(d10, al1, bb.x, bb.y); mma(d11, al1, bb.z, bb.w);                   \
        bb = ldmx4(sb_ + OFF_BLO + boff0);                                      \
        mma(d00, ah0, bb.x, bb.y); mma(d01, ah0, bb.z, bb.w);                   \
        mma(d10, ah1, bb.x, bb.y); mma(d11, ah1, bb.z, bb.w);                   \
        bb = ldmx4(sb_ + OFF_BHI + boff1);                                      \
        mma(d02, ah0, bb.x, bb.y); mma(d03, ah0, bb.z, bb.w);                   \
        mma(d12, ah1, bb.x, bb.y); mma(d13, ah1, bb.z, bb.w);                   \
        mma(d02, al0, bb.x, bb.y); mma(d03, al0, bb.z, bb.w);                   \
        mma(d12, al1, bb.x, bb.y); mma(d13, al1, bb.z, bb.w);                   \
        bb = ldmx4(sb_ + OFF_BLO + boff1);                                      \
        mma(d02, ah0, bb.x, bb.y); mma(d03, ah0, bb.z, bb.w);                   \
        mma(d12, ah1, bb.x, bb.y); mma(d13, ah1, bb.z, bb.w);                   \
    }

// store one k-step's operands (already in regs) into stage buffer
#define STORE_STAGE(SBASE, PA, PBA, PBB)                                        \
    {   uint2 h_, l_, h2_, l2_;                                                 \
        split4(PA, h_, l_);                                                     \
        sts8((SBASE) + OFF_AHI + sA, h_.x, h_.y);                               \
        sts8((SBASE) + OFF_ALO + sA, l_.x, l_.y);                               \
        split4(PBA, h_, l_); split4(PBB, h2_, l2_);                             \
        sts16((SBASE) + OFF_BHI + sB, h_.x, h_.y, h2_.x, h2_.y);                \
        sts16((SBASE) + OFF_BLO + sB, l_.x, l_.y, l2_.x, l2_.y);                \
    }

__device__ __forceinline__ void gemm_core(
    const float* __restrict__ A, int lda,
    const float* __restrict__ B, int ldb,
    const float* __restrict__ bias,
    float* __restrict__ C, int ldc, int do_stats,
    size_t m0, size_t n0, uint8_t* smem_raw) {
    uint32_t smb = smem_u32(smem_raw);

    int tid = threadIdx.x, wid = tid >> 5, lane = tid & 31;
    int warp_m = wid >> 2, warp_n = wid & 3;

    // loaders: A: 64 rows x 4 chunks -> 1 chunk/thread.
    //          B: 128 rows x 4 chunks -> 2 adjacent chunks/thread (32B).
    int arow = tid >> 2, ac4 = tid & 3;
    int brow = tid >> 1, bhalf = tid & 1;
    const float* aptr = A + (m0 + (size_t)arow) * (size_t)lda + ac4 * 4;
    const float* bptr = B + (n0 + (size_t)brow) * (size_t)ldb + bhalf * 8;
    uint32_t sA = (uint32_t)(arow * 48 + ac4 * 8);
    uint32_t sB = (uint32_t)(brow * 48 + bhalf * 16);

    // ldmatrix lane addressing
    int q = lane >> 3, li = lane & 7;
    uint32_t aoff0 = (uint32_t)((warp_m * 32 + 0  + (q & 1) * 8 + li) * 48 + (q >> 1) * 16);
    uint32_t aoff1 = (uint32_t)((warp_m * 32 + 16 + (q & 1) * 8 + li) * 48 + (q >> 1) * 16);
    uint32_t boff0 = (uint32_t)((warp_n * 32 + 0  + (q >> 1) * 8 + li) * 48 + (q & 1) * 16);
    uint32_t boff1 = (uint32_t)((warp_n * 32 + 16 + (q >> 1) * 8 + li) * 48 + (q & 1) * 16);

    F4 d00, d01, d02, d03, d10, d11, d12, d13;
    d00.x = d00.y = d00.z = d00.w = 0.f;
    d01 = d00; d02 = d00; d03 = d00;
    d10 = d00; d11 = d00; d12 = d00; d13 = d00;

    // prefetch k-steps 0 and 1
    float4 pa0  = *(const float4*)(aptr);
    float4 pb0a = *(const float4*)(bptr);
    float4 pb0b = *(const float4*)(bptr + 4);
    float4 pa1  = *(const float4*)(aptr + 16);
    float4 pb1a = *(const float4*)(bptr + 16);
    float4 pb1b = *(const float4*)(bptr + 20);

#pragma unroll 1
    for (int s = 0; s < KSTEPS; s += 2) {
        // even step -> stage 0
        STORE_STAGE(smb, pa0, pb0a, pb0b)
        if (s + 2 < KSTEPS) {
            pa0  = *(const float4*)(aptr + (s + 2) * 16);
            pb0a = *(const float4*)(bptr + (s + 2) * 16);
            pb0b = *(const float4*)(bptr + (s + 2) * 16 + 4);
        }
        __syncthreads();
        MMA_STEP(smb)
        // odd step -> stage 1
        STORE_STAGE(smb + STAGE_B, pa1, pb1a, pb1b)
        if (s + 3 < KSTEPS) {
            pa1  = *(const float4*)(aptr + (s + 3) * 16);
            pb1a = *(const float4*)(bptr + (s + 3) * 16);
            pb1b = *(const float4*)(bptr + (s + 3) * 16 + 4);
        }
        __syncthreads();
        MMA_STEP(smb + STAGE_B)
    }

    // epilogue
    int groupl = lane >> 2, subl = lane & 3;
    int colbase = (int)n0 + warp_n * 32 + subl * 2;

#pragma unroll
    for (int half = 0; half < 2; half++) {
        {
            size_t r = m0 + (size_t)(warp_m * 32 + 0 + half * 8 + groupl);
            float* crow = C + r * (size_t)ldc + colbase;
            float s = 0.f, sq = 0.f;
            EPI_ONE(d00, 0) EPI_ONE(d01, 1) EPI_ONE(d02, 2) EPI_ONE(d03, 3)
            if (do_stats) {
                s  += __shfl_xor_sync(0xffffffffu, s, 1);
                s  += __shfl_xor_sync(0xffffffffu, s, 2);
                sq += __shfl_xor_sync(0xffffffffu, sq, 1);
                sq += __shfl_xor_sync(0xffffffffu, sq, 2);
                if (subl == 0) { atomicAdd(&g_rowsum[r], s); atomicAdd(&g_rowsq[r], sq); }
            }
        }
        {
            size_t r = m0 + (size_t)(warp_m * 32 + 16 + half * 8 + groupl);
            float* crow = C + r * (size_t)ldc + colbase;
            float s = 0.f, sq = 0.f;
            EPI_ONE(d10, 0) EPI_ONE(d11, 1) EPI_ONE(d12, 2) EPI_ONE(d13, 3)
            if (do_stats) {
                s  += __shfl_xor_sync(0xffffffffu, s, 1);
                s  += __shfl_xor_sync(0xffffffffu, s, 2);
                sq += __shfl_xor_sync(0xffffffffu, sq, 1);
                sq += __shfl_xor_sync(0xffffffffu, sq, 2);
                if (subl == 0) { atomicAdd(&g_rowsum[r], s); atomicAdd(&g_rowsq[r], sq); }
            }
        }
    }
}

// logits GEMM (generic)
__global__ __launch_bounds__(256, 2)
void mma_gemm(const float* __restrict__ A, int lda,
              const float* __restrict__ B, int ldb,
              const float* __restrict__ bias,
              float* __restrict__ C, int ldc, int do_stats) {
    __shared__ __align__(16) uint8_t smbuf[2 * STAGE_B];    // 36 KB
    gemm_core(A, lda, B, ldb, bias, C, ldc, do_stats,
              (size_t)blockIdx.y * 64, (size_t)blockIdx.x * 128, smbuf);
}

// merged qproj + kproj: z=0 -> qproj (8 M-blocks of 64), z=1 -> kproj (16)
__global__ __launch_bounds__(256, 2)
void qk_gemm(const float* __restrict__ tgt, const float* __restrict__ src,
             const float* __restrict__ W_attn, const float* __restrict__ b_attn) {
    __shared__ __align__(16) uint8_t smbuf[2 * STAGE_B];
    if (blockIdx.z == 0) {
        if (blockIdx.y >= NROW / 64) return;
        gemm_core(tgt, Dd, W_attn, 2 * Dd, b_attn, g_qproj, Dd, 0,
                  (size_t)blockIdx.y * 64, (size_t)blockIdx.x * 128, smbuf);
    } else {
        gemm_core(src, Dd, W_attn + Dd, 2 * Dd, nullptr, g_kproj, Dd, 0,
                  (size_t)blockIdx.y * 64, (size_t)blockIdx.x * 128, smbuf);
    }
}

// ---------------- fused additive attention -----------------------------------
__global__ __launch_bounds__(256)
void attn_kernel(const float* __restrict__ src, const float* __restrict__ v_w,
                 const float* __restrict__ W_lin, const float* __restrict__ b_lin) {
    __shared__ float qp[Dd];
    __shared__ float vw[Dd];
    __shared__ float sraw[TK];
    __shared__ float sprob[TK];
    __shared__ float scr[9];

    int row = blockIdx.x;
    int b = row >> 6;
    int tid = threadIdx.x, lane = tid & 31, w = tid >> 5;

    for (int i = tid; i < Dd; i += 256) {
        qp[i] = g_qproj[row * Dd + i];
        vw[i] = v_w[i];
    }
    float tm = g_tgtmask[row];
    __syncthreads();

    float qpr[16], vwr[16];
#pragma unroll
    for (int j = 0; j < 16; j++) {
        qpr[j] = qp[lane + 32 * j];
        vwr[j] = vw[lane + 32 * j];
    }

    for (int k = w; k < TK; k += 8) {
        const float* kp = g_kproj + ((size_t)(b * TK + k)) * Dd;
        float acc = 0.f;
#pragma unroll
        for (int j = 0; j < 16; j++)
            acc += tanh_fast(qpr[j] + __ldg(kp + lane + 32 * j)) * vwr[j];
        acc = warp_sum(acc);
        if (lane == 0) sraw[k] = acc;
    }
    __syncthreads();

    float raw = 0.f, smk = 0.f;
    if (tid < TK) { raw = sraw[tid]; smk = g_srcmask[b * TK + tid]; }
    float masked = (tid < TK) ? ((smk == 0.f) ? -1e30f : raw) : -1e30f;
    float mx = block_max256(masked, scr);
    float e = (tid < TK) ? __expf(masked - mx) : 0.f;
    float ssum = block_sum256(e, scr);
    if (tid < TK) sprob[tid] = e / ssum;

    float oa = (tid < TK) ? raw * smk * tm : 0.f;
    float osum = block_sum256(oa, scr);
    float osq  = block_sum256(oa * oa, scr);

    float zacc = 0.f;
    for (int dd = tid; dd < Dd; dd += 256) {
        float wv = 0.f;
        const float* sp = src + ((size_t)b * TK) * Dd + dd;
#pragma unroll 4
        for (int k = 0; k < TK; k++) wv = fmaf(sprob[k], sp[(size_t)k * Dd], wv);
        wv *= tm;
        zacc = fmaf(wv, W_lin[dd], zacc);
    }
    float z = block_sum256(zacc, scr);
    if (tid == 0) g_p[row] = 1.f / (1.f + __expf(-(z + b_lin[0])));

    float mean = osum * (1.f / (float)TK);
    float var = osq * (1.f / (float)TK) - mean * mean;
    float inv = rsqrtf(var + 1e-5f);
    if (tid < TK) g_att[row * TK + tid] = (oa - mean) * inv;
}

// ---------------- combine (in-place on out) + scatter -------------------------
__global__ __launch_bounds__(256)
void combine_kernel(float* __restrict__ out) {
    int row = blockIdx.x;
    float mean = g_rowsum[row] * (1.f / (float)Vv);
    float var = g_rowsq[row] * (1.f / (float)Vv) - mean * mean;
    float inv = rsqrtf(var + 1e-5f);
    float pv = g_p[row];
    float a = inv * pv;
    float c = -mean * inv * pv;
    float4* op = (float4*)(out + (size_t)row * EXTN);
    for (int i = threadIdx.x; i < Vv / 4; i += 256) {
        float4 v = op[i];
        v.x = fmaf(v.x, a, c); v.y = fmaf(v.y, a, c);
        v.z = fmaf(v.z, a, c); v.w = fmaf(v.w, a, c);
        op[i] = v;
    }
    for (int j = Vv + threadIdx.x; j < EXTN; j += 256)
        out[(size_t)row * EXTN + j] = 0.f;
}

// src_map_idx is int32 on the wire (JAX x64-disabled); bounds-guarded.
__global__ void scatter_kernel(float* __restrict__ out,
                               const int* __restrict__ map) {
    int row = blockIdx.x;
    int b = row >> 6;
    float q = 1.f - g_p[row];
    for (int k = threadIdx.x; k < TK; k += blockDim.x) {
        int idx = map[b * TK + k];
        if (idx >= 0 && idx < EXTN)
            atomicAdd(out + (size_t)row * EXTN + (size_t)idx,
                      q * g_att[row * TK + k]);
    }
}

// ---------------- launch ------------------------------------------------------
extern "C" void kernel_launch(void* const* d_in, const int* in_sizes, int n_in,
                              void* d_out, int out_size) {
    const float* tgt    = (const float*)d_in[0];
    const float* src    = (const float*)d_in[1];
    const int*   mp     = (const int*)d_in[2];
    const float* W_out  = (const float*)d_in[3];
    const float* b_out  = (const float*)d_in[4];
    const float* W_attn = (const float*)d_in[5];
    const float* b_attn = (const float*)d_in[6];
    const float* v_w    = (const float*)d_in[7];
    const float* W_lin  = (const float*)d_in[8];
    const float* b_lin  = (const float*)d_in[9];
    float* out = (float*)d_out;

    init_kernel<<<2, 256>>>();
    mask_kernel<<<NROW + NKROW, 128>>>(tgt, src);

    // qproj + kproj merged (z=0: qproj 8 M-blocks; z=1: kproj 16 M-blocks)
    qk_gemm<<<dim3(Dd / 128, NKROW / 64, 2), 256>>>(tgt, src, W_attn, b_attn);

    // logits = tgt @ W_out^T + b_out, written straight into out (ldc = EXTN)
    mma_gemm<<<dim3(Vv / 128, NROW / 64), 256>>>(
        tgt, Dd, W_out, Dd, b_out, out, EXTN, 1);

    attn_kernel<<<NROW, 256>>>(src, v_w, W_lin, b_lin);
    combine_kernel<<<NROW, 256>>>(out);
    scatter_kernel<<<NROW, 128>>>(out, mp);
}